// round 1
// baseline (speedup 1.0000x reference)
#include <cuda_runtime.h>
#include <cuda_bf16.h>

// ---------------- problem constants ----------------
#define NMAX 100000
#define EMAX 1600000
#define INF 512
#define D1 64      // H1*F1 = 8*8
#define H1N 8
#define D2 40      // H2*F2 = 1*40

// ---------------- device scratch (no dynamic alloc allowed) ----------------
__device__ __align__(16) float g_h1  [NMAX * D1];  // layer1 pre-aggregation features
__device__ __align__(16) float g_el1 [NMAX * H1N];
__device__ __align__(16) float g_er1 [NMAX * H1N];
__device__ __align__(16) float g_s1  [NMAX * H1N]; // softmax denominators
__device__ __align__(16) float g_agg1[NMAX * D1];  // layer1 aggregated
__device__ __align__(16) float g_h2  [NMAX * D2];  // layer2 pre-aggregation features
__device__ __align__(16) float g_el2 [NMAX];
__device__ __align__(16) float g_er2 [NMAX];
__device__ __align__(16) float g_s2  [NMAX];
__device__ __align__(16) float g_agg2[NMAX * D2];

// ---------------- helpers ----------------
__device__ __forceinline__ unsigned long long pk(float a, float b) {
    unsigned long long r;
    asm("mov.b64 %0, {%1, %2};" : "=l"(r) : "f"(a), "f"(b));
    return r;
}
__device__ __forceinline__ float2 upk(unsigned long long v) {
    float2 r;
    asm("mov.b64 {%0, %1}, %2;" : "=f"(r.x), "=f"(r.y) : "l"(v));
    return r;
}
__device__ __forceinline__ void fma2(unsigned long long& d, unsigned long long a, unsigned long long b) {
    asm("fma.rn.f32x2 %0, %1, %2, %3;" : "=l"(d) : "l"(a), "l"(b), "l"(d));
}
__device__ __forceinline__ void red4(float* p, float4 v) {
    asm volatile("red.global.add.v4.f32 [%0], {%1, %2, %3, %4};"
                 :: "l"(p), "f"(v.x), "f"(v.y), "f"(v.z), "f"(v.w) : "memory");
}
__device__ __forceinline__ float lrelu(float v) { return v >= 0.f ? v : 0.2f * v; }
__device__ __forceinline__ float eluf(float v)  { return v > 0.f ? v : expm1f(v); }

// ---------------- K0: zero aggregation buffers ----------------
__global__ void k_zero(int n) {
    int i = blockIdx.x * 256 + threadIdx.x;
    if (i < n * D1) g_agg1[i] = 0.f;
    if (i < n * D2) g_agg2[i] = 0.f;
    if (i < n * H1N) g_s1[i] = 0.f;
    if (i < n) g_s2[i] = 0.f;
}

// ---------------- K1: h1 = x @ W1   (100k x 512) @ (512 x 64) ----------------
// 128x64 tile per block, 4x8 microtile per thread, packed f32x2 FMA.
__global__ __launch_bounds__(256) void k_gemm1(const float* __restrict__ x,
                                               const float* __restrict__ W1, int n) {
    __shared__ __align__(16) float xs[128][40];   // stride 40 floats (160B, 16B-aligned)
    __shared__ __align__(16) float ws[32][64];
    const int tx = threadIdx.x;
    const int row0 = blockIdx.x * 128;
    const int rg = (tx >> 3) * 4;       // 0..124
    const int cg = (tx & 7) * 8;        // 0..56

    unsigned long long acc[4][4];
#pragma unroll
    for (int i = 0; i < 4; i++)
#pragma unroll
        for (int j = 0; j < 4; j++) acc[i][j] = 0ull;

    for (int k0 = 0; k0 < INF; k0 += 32) {
        // load x tile: 128 rows x 32 k  (1024 float4, 4 per thread)
#pragma unroll
        for (int it = 0; it < 4; it++) {
            int slot = tx + it * 256;
            int r = slot >> 3;
            int kk = (slot & 7) << 2;
            float4 v = make_float4(0.f, 0.f, 0.f, 0.f);
            int grow = row0 + r;
            if (grow < n) v = *(const float4*)(x + (size_t)grow * INF + k0 + kk);
            *(float4*)&xs[r][kk] = v;
        }
        // load W tile: 32 k x 64 cols (512 float4, 2 per thread)
#pragma unroll
        for (int it = 0; it < 2; it++) {
            int slot = tx + it * 256;
            int kk = slot >> 4;
            int cc = (slot & 15) << 2;
            *(float4*)&ws[kk][cc] = *(const float4*)(W1 + (size_t)(k0 + kk) * D1 + cc);
        }
        __syncthreads();

#pragma unroll
        for (int k4 = 0; k4 < 32; k4 += 4) {
            float4 A[4];
#pragma unroll
            for (int i = 0; i < 4; i++) A[i] = *(const float4*)&xs[rg + i][k4];
#pragma unroll
            for (int kk = 0; kk < 4; kk++) {
                ulonglong2 B0 = *(const ulonglong2*)&ws[k4 + kk][cg];
                ulonglong2 B1 = *(const ulonglong2*)&ws[k4 + kk][cg + 4];
#pragma unroll
                for (int i = 0; i < 4; i++) {
                    float ai = ((const float*)&A[i])[kk];
                    unsigned long long pa = pk(ai, ai);
                    fma2(acc[i][0], pa, B0.x);
                    fma2(acc[i][1], pa, B0.y);
                    fma2(acc[i][2], pa, B1.x);
                    fma2(acc[i][3], pa, B1.y);
                }
            }
        }
        __syncthreads();
    }

#pragma unroll
    for (int i = 0; i < 4; i++) {
        int grow = row0 + rg + i;
        if (grow < n) {
            float2 v0 = upk(acc[i][0]), v1 = upk(acc[i][1]);
            float2 v2 = upk(acc[i][2]), v3 = upk(acc[i][3]);
            *(float4*)(g_h1 + (size_t)grow * D1 + cg)     = make_float4(v0.x, v0.y, v1.x, v1.y);
            *(float4*)(g_h1 + (size_t)grow * D1 + cg + 4) = make_float4(v2.x, v2.y, v3.x, v3.y);
        }
    }
}

// ---------------- K2: per-node attention dots el1/er1 ----------------
__global__ __launch_bounds__(256) void k_el1(const float* __restrict__ al1,
                                             const float* __restrict__ ar1, int n) {
    __shared__ float sa[64], sr[64];
    if (threadIdx.x < 64) { sa[threadIdx.x] = al1[threadIdx.x]; sr[threadIdx.x] = ar1[threadIdx.x]; }
    __syncthreads();
    int nid = blockIdx.x * 256 + threadIdx.x;
    if (nid >= n) return;
    const float4* hp = (const float4*)(g_h1 + (size_t)nid * D1);
    float el[8], er[8];
#pragma unroll
    for (int h = 0; h < 8; h++) {
        float4 t0 = hp[h * 2], t1 = hp[h * 2 + 1];
        int b = h * 8;
        el[h] = t0.x*sa[b] + t0.y*sa[b+1] + t0.z*sa[b+2] + t0.w*sa[b+3]
              + t1.x*sa[b+4] + t1.y*sa[b+5] + t1.z*sa[b+6] + t1.w*sa[b+7];
        er[h] = t0.x*sr[b] + t0.y*sr[b+1] + t0.z*sr[b+2] + t0.w*sr[b+3]
              + t1.x*sr[b+4] + t1.y*sr[b+5] + t1.z*sr[b+6] + t1.w*sr[b+7];
    }
    *(float4*)(g_el1 + (size_t)nid * 8)     = make_float4(el[0], el[1], el[2], el[3]);
    *(float4*)(g_el1 + (size_t)nid * 8 + 4) = make_float4(el[4], el[5], el[6], el[7]);
    *(float4*)(g_er1 + (size_t)nid * 8)     = make_float4(er[0], er[1], er[2], er[3]);
    *(float4*)(g_er1 + (size_t)nid * 8 + 4) = make_float4(er[4], er[5], er[6], er[7]);
}

// ---------------- K3: layer1 edge exp-sum ----------------
__global__ __launch_bounds__(256) void k_esum1(const int* __restrict__ src,
                                               const int* __restrict__ dst, int e) {
    int i = blockIdx.x * 256 + threadIdx.x;
    if (i >= e) return;
    int s = src[i], d = dst[i];
    float4 a0 = *(const float4*)(g_el1 + (size_t)s * 8);
    float4 a1 = *(const float4*)(g_el1 + (size_t)s * 8 + 4);
    float4 b0 = *(const float4*)(g_er1 + (size_t)d * 8);
    float4 b1 = *(const float4*)(g_er1 + (size_t)d * 8 + 4);
    float4 e0 = make_float4(__expf(lrelu(a0.x + b0.x)), __expf(lrelu(a0.y + b0.y)),
                            __expf(lrelu(a0.z + b0.z)), __expf(lrelu(a0.w + b0.w)));
    float4 e1 = make_float4(__expf(lrelu(a1.x + b1.x)), __expf(lrelu(a1.y + b1.y)),
                            __expf(lrelu(a1.z + b1.z)), __expf(lrelu(a1.w + b1.w)));
    red4(g_s1 + (size_t)d * 8, e0);
    red4(g_s1 + (size_t)d * 8 + 4, e1);
}

// ---------------- K4: layer1 edge aggregation ----------------
__global__ __launch_bounds__(256) void k_eagg1(const int* __restrict__ src,
                                               const int* __restrict__ dst, int e) {
    int i = blockIdx.x * 256 + threadIdx.x;
    if (i >= e) return;
    int s = src[i], d = dst[i];
    float4 a0 = *(const float4*)(g_el1 + (size_t)s * 8);
    float4 a1 = *(const float4*)(g_el1 + (size_t)s * 8 + 4);
    float4 b0 = *(const float4*)(g_er1 + (size_t)d * 8);
    float4 b1 = *(const float4*)(g_er1 + (size_t)d * 8 + 4);
    float4 s0 = *(const float4*)(g_s1 + (size_t)d * 8);
    float4 s1 = *(const float4*)(g_s1 + (size_t)d * 8 + 4);
    float alpha[8];
    alpha[0] = __fdividef(__expf(lrelu(a0.x + b0.x)), s0.x);
    alpha[1] = __fdividef(__expf(lrelu(a0.y + b0.y)), s0.y);
    alpha[2] = __fdividef(__expf(lrelu(a0.z + b0.z)), s0.z);
    alpha[3] = __fdividef(__expf(lrelu(a0.w + b0.w)), s0.w);
    alpha[4] = __fdividef(__expf(lrelu(a1.x + b1.x)), s1.x);
    alpha[5] = __fdividef(__expf(lrelu(a1.y + b1.y)), s1.y);
    alpha[6] = __fdividef(__expf(lrelu(a1.z + b1.z)), s1.z);
    alpha[7] = __fdividef(__expf(lrelu(a1.w + b1.w)), s1.w);
    const float4* hp = (const float4*)(g_h1 + (size_t)s * D1);
    float* op = g_agg1 + (size_t)d * D1;
#pragma unroll
    for (int j = 0; j < 16; j++) {
        float al = alpha[j >> 1];
        float4 hv = hp[j];
        red4(op + j * 4, make_float4(hv.x * al, hv.y * al, hv.z * al, hv.w * al));
    }
}

// ---------------- K5: node: ELU(agg1+b1), GEMM2 (64->40), el2/er2 ----------------
__global__ __launch_bounds__(256) void k_node2(const float* __restrict__ W2,
                                               const float* __restrict__ al2,
                                               const float* __restrict__ ar2,
                                               const float* __restrict__ b1, int n) {
    __shared__ float w2s[64 * 40];
    __shared__ float sal[40], sar[40], sb1[64];
    for (int i = threadIdx.x; i < 64 * 40; i += 256) w2s[i] = W2[i];
    if (threadIdx.x < 40) { sal[threadIdx.x] = al2[threadIdx.x]; sar[threadIdx.x] = ar2[threadIdx.x]; }
    if (threadIdx.x < 64) sb1[threadIdx.x] = b1[threadIdx.x];
    __syncthreads();
    int nid = blockIdx.x * 256 + threadIdx.x;
    if (nid >= n) return;
    float v[64];
    const float4* ap = (const float4*)(g_agg1 + (size_t)nid * D1);
#pragma unroll
    for (int j = 0; j < 16; j++) {
        float4 t = ap[j];
        v[j * 4 + 0] = eluf(t.x + sb1[j * 4 + 0]);
        v[j * 4 + 1] = eluf(t.y + sb1[j * 4 + 1]);
        v[j * 4 + 2] = eluf(t.z + sb1[j * 4 + 2]);
        v[j * 4 + 3] = eluf(t.w + sb1[j * 4 + 3]);
    }
    float ela = 0.f, era = 0.f;
    float* hp = g_h2 + (size_t)nid * D2;
    for (int c = 0; c < D2; c++) {
        float acc = 0.f;
#pragma unroll
        for (int k = 0; k < 64; k++) acc = fmaf(v[k], w2s[k * D2 + c], acc);
        hp[c] = acc;
        ela = fmaf(acc, sal[c], ela);
        era = fmaf(acc, sar[c], era);
    }
    g_el2[nid] = ela;
    g_er2[nid] = era;
}

// ---------------- K6: layer2 edge exp-sum ----------------
__global__ __launch_bounds__(256) void k_esum2(const int* __restrict__ src,
                                               const int* __restrict__ dst, int e) {
    int i = blockIdx.x * 256 + threadIdx.x;
    if (i >= e) return;
    int s = src[i], d = dst[i];
    float ex = __expf(lrelu(g_el2[s] + g_er2[d]));
    atomicAdd(g_s2 + d, ex);
}

// ---------------- K7: layer2 edge aggregation ----------------
__global__ __launch_bounds__(256) void k_eagg2(const int* __restrict__ src,
                                               const int* __restrict__ dst, int e) {
    int i = blockIdx.x * 256 + threadIdx.x;
    if (i >= e) return;
    int s = src[i], d = dst[i];
    float alpha = __fdividef(__expf(lrelu(g_el2[s] + g_er2[d])), g_s2[d]);
    const float4* hp = (const float4*)(g_h2 + (size_t)s * D2);
    float* op = g_agg2 + (size_t)d * D2;
#pragma unroll
    for (int j = 0; j < 10; j++) {
        float4 hv = hp[j];
        red4(op + j * 4, make_float4(hv.x * alpha, hv.y * alpha, hv.z * alpha, hv.w * alpha));
    }
}

// ---------------- K8: final bias + log_softmax ----------------
__global__ __launch_bounds__(256) void k_lsm(const float* __restrict__ b2,
                                             float* __restrict__ out, int n) {
    __shared__ float sb2[40];
    if (threadIdx.x < 40) sb2[threadIdx.x] = b2[threadIdx.x];
    __syncthreads();
    int nid = blockIdx.x * 256 + threadIdx.x;
    if (nid >= n) return;
    float v[40];
    const float4* ap = (const float4*)(g_agg2 + (size_t)nid * D2);
    float m = -1e30f;
#pragma unroll
    for (int j = 0; j < 10; j++) {
        float4 t = ap[j];
        v[j*4+0] = t.x + sb2[j*4+0];
        v[j*4+1] = t.y + sb2[j*4+1];
        v[j*4+2] = t.z + sb2[j*4+2];
        v[j*4+3] = t.w + sb2[j*4+3];
        m = fmaxf(m, fmaxf(fmaxf(v[j*4+0], v[j*4+1]), fmaxf(v[j*4+2], v[j*4+3])));
    }
    float s = 0.f;
#pragma unroll
    for (int j = 0; j < 40; j++) s += __expf(v[j] - m);
    float lse = m + logf(s);
    float4* op = (float4*)(out + (size_t)nid * D2);
#pragma unroll
    for (int j = 0; j < 10; j++)
        op[j] = make_float4(v[j*4+0] - lse, v[j*4+1] - lse, v[j*4+2] - lse, v[j*4+3] - lse);
}

// ---------------- launch ----------------
extern "C" void kernel_launch(void* const* d_in, const int* in_sizes, int n_in,
                              void* d_out, int out_size) {
    const float* x   = (const float*)d_in[0];
    const int*   src = (const int*)d_in[1];
    const int*   dst = (const int*)d_in[2];
    const float* W1  = (const float*)d_in[3];
    const float* al1 = (const float*)d_in[4];
    const float* ar1 = (const float*)d_in[5];
    const float* b1  = (const float*)d_in[6];
    const float* W2  = (const float*)d_in[7];
    const float* al2 = (const float*)d_in[8];
    const float* ar2 = (const float*)d_in[9];
    const float* b2  = (const float*)d_in[10];

    int n = in_sizes[0] / INF;
    int e = in_sizes[1];

    int nb_zero = (n * D1 + 255) / 256;
    int nb_node = (n + 255) / 256;
    int nb_edge = (e + 255) / 256;
    int nb_gemm = (n + 127) / 128;

    k_zero<<<nb_zero, 256>>>(n);
    k_gemm1<<<nb_gemm, 256>>>(x, W1, n);
    k_el1<<<nb_node, 256>>>(al1, ar1, n);
    k_esum1<<<nb_edge, 256>>>(src, dst, e);
    k_eagg1<<<nb_edge, 256>>>(src, dst, e);
    k_node2<<<nb_node, 256>>>(W2, al2, ar2, b1, n);
    k_esum2<<<nb_edge, 256>>>(src, dst, e);
    k_eagg2<<<nb_edge, 256>>>(src, dst, e);
    k_lsm<<<nb_node, 256>>>(b2, (float*)d_out, n);
}

// round 2
// speedup vs baseline: 1.3910x; 1.3910x over previous
#include <cuda_runtime.h>
#include <cuda_bf16.h>

// ---------------- problem constants ----------------
#define NMAX 100000
#define EMAX 1600000
#define INF 512
#define D1 64      // H1*F1 = 8*8
#define H1N 8
#define D2 40      // H2*F2 = 1*40

// ---------------- device scratch ----------------
__device__ __align__(16) float g_h1  [NMAX * D1];
__device__ __align__(16) float g_el1 [NMAX * H1N];
__device__ __align__(16) float g_er1 [NMAX * H1N];
__device__ __align__(16) float g_s1  [NMAX * H1N];
__device__ __align__(16) float g_agg1[NMAX * D1];
__device__ __align__(16) float g_h2  [NMAX * D2];
__device__ __align__(16) float g_el2 [NMAX];
__device__ __align__(16) float g_er2 [NMAX];
__device__ __align__(16) float g_s2  [NMAX];
__device__ __align__(16) float g_agg2[NMAX * D2];

// ---------------- helpers ----------------
__device__ __forceinline__ unsigned long long pk(float a, float b) {
    unsigned long long r;
    asm("mov.b64 %0, {%1, %2};" : "=l"(r) : "f"(a), "f"(b));
    return r;
}
__device__ __forceinline__ float2 upk(unsigned long long v) {
    float2 r;
    asm("mov.b64 {%0, %1}, %2;" : "=f"(r.x), "=f"(r.y) : "l"(v));
    return r;
}
__device__ __forceinline__ void fma2(unsigned long long& d, unsigned long long a, unsigned long long b) {
    asm("fma.rn.f32x2 %0, %1, %2, %3;" : "=l"(d) : "l"(a), "l"(b), "l"(d));
}
__device__ __forceinline__ void red4(float* p, float4 v) {
    asm volatile("red.global.add.v4.f32 [%0], {%1, %2, %3, %4};"
                 :: "l"(p), "f"(v.x), "f"(v.y), "f"(v.z), "f"(v.w) : "memory");
}
__device__ __forceinline__ void redf(float* p, float v) {
    asm volatile("red.global.add.f32 [%0], %1;" :: "l"(p), "f"(v) : "memory");
}
__device__ __forceinline__ float lrelu(float v) { return v >= 0.f ? v : 0.2f * v; }
__device__ __forceinline__ float eluf(float v)  { return v > 0.f ? v : expm1f(v); }

// ---------------- K0: zero accumulators (vectorized) ----------------
__global__ void k_zero(int n) {
    int i = blockIdx.x * 256 + threadIdx.x;            // float4 index
    float4 z = make_float4(0.f, 0.f, 0.f, 0.f);
    if (i < n * (D1 / 4)) ((float4*)g_agg1)[i] = z;
    if (i < n * (D2 / 4)) ((float4*)g_agg2)[i] = z;
    if (i < n * (H1N / 4)) ((float4*)g_s1)[i] = z;
    if (i * 4 < n) {
        int lim = n - i * 4;
        float* p = g_s2 + i * 4;
        if (lim >= 4) *(float4*)p = z;
        else for (int j = 0; j < lim; j++) p[j] = 0.f;
    }
}

// ---------------- K1: h1 = x @ W1   (100k x 512) @ (512 x 64), f32x2 FMA ----------------
__global__ __launch_bounds__(256) void k_gemm1(const float* __restrict__ x,
                                               const float* __restrict__ W1, int n) {
    __shared__ __align__(16) float xs[128][40];
    __shared__ __align__(16) float ws[32][64];
    const int tx = threadIdx.x;
    const int row0 = blockIdx.x * 128;
    const int rg = (tx >> 3) * 4;
    const int cg = (tx & 7) * 8;

    unsigned long long acc[4][4];
#pragma unroll
    for (int i = 0; i < 4; i++)
#pragma unroll
        for (int j = 0; j < 4; j++) acc[i][j] = 0ull;

    for (int k0 = 0; k0 < INF; k0 += 32) {
#pragma unroll
        for (int it = 0; it < 4; it++) {
            int slot = tx + it * 256;
            int r = slot >> 3;
            int kk = (slot & 7) << 2;
            float4 v = make_float4(0.f, 0.f, 0.f, 0.f);
            int grow = row0 + r;
            if (grow < n) v = *(const float4*)(x + (size_t)grow * INF + k0 + kk);
            *(float4*)&xs[r][kk] = v;
        }
#pragma unroll
        for (int it = 0; it < 2; it++) {
            int slot = tx + it * 256;
            int kk = slot >> 4;
            int cc = (slot & 15) << 2;
            *(float4*)&ws[kk][cc] = *(const float4*)(W1 + (size_t)(k0 + kk) * D1 + cc);
        }
        __syncthreads();

#pragma unroll
        for (int k4 = 0; k4 < 32; k4 += 4) {
            float4 A[4];
#pragma unroll
            for (int i = 0; i < 4; i++) A[i] = *(const float4*)&xs[rg + i][k4];
#pragma unroll
            for (int kk = 0; kk < 4; kk++) {
                ulonglong2 B0 = *(const ulonglong2*)&ws[k4 + kk][cg];
                ulonglong2 B1 = *(const ulonglong2*)&ws[k4 + kk][cg + 4];
#pragma unroll
                for (int i = 0; i < 4; i++) {
                    float ai = ((const float*)&A[i])[kk];
                    unsigned long long pa = pk(ai, ai);
                    fma2(acc[i][0], pa, B0.x);
                    fma2(acc[i][1], pa, B0.y);
                    fma2(acc[i][2], pa, B1.x);
                    fma2(acc[i][3], pa, B1.y);
                }
            }
        }
        __syncthreads();
    }

#pragma unroll
    for (int i = 0; i < 4; i++) {
        int grow = row0 + rg + i;
        if (grow < n) {
            float2 v0 = upk(acc[i][0]), v1 = upk(acc[i][1]);
            float2 v2 = upk(acc[i][2]), v3 = upk(acc[i][3]);
            *(float4*)(g_h1 + (size_t)grow * D1 + cg)     = make_float4(v0.x, v0.y, v1.x, v1.y);
            *(float4*)(g_h1 + (size_t)grow * D1 + cg + 4) = make_float4(v2.x, v2.y, v3.x, v3.y);
        }
    }
}

// ---------------- K2: per-node attention dots el1/er1 ----------------
__global__ __launch_bounds__(256) void k_el1(const float* __restrict__ al1,
                                             const float* __restrict__ ar1, int n) {
    __shared__ float sa[64], sr[64];
    if (threadIdx.x < 64) { sa[threadIdx.x] = al1[threadIdx.x]; sr[threadIdx.x] = ar1[threadIdx.x]; }
    __syncthreads();
    int nid = blockIdx.x * 256 + threadIdx.x;
    if (nid >= n) return;
    const float4* hp = (const float4*)(g_h1 + (size_t)nid * D1);
    float el[8], er[8];
#pragma unroll
    for (int h = 0; h < 8; h++) {
        float4 t0 = hp[h * 2], t1 = hp[h * 2 + 1];
        int b = h * 8;
        el[h] = t0.x*sa[b] + t0.y*sa[b+1] + t0.z*sa[b+2] + t0.w*sa[b+3]
              + t1.x*sa[b+4] + t1.y*sa[b+5] + t1.z*sa[b+6] + t1.w*sa[b+7];
        er[h] = t0.x*sr[b] + t0.y*sr[b+1] + t0.z*sr[b+2] + t0.w*sr[b+3]
              + t1.x*sr[b+4] + t1.y*sr[b+5] + t1.z*sr[b+6] + t1.w*sr[b+7];
    }
    *(float4*)(g_el1 + (size_t)nid * 8)     = make_float4(el[0], el[1], el[2], el[3]);
    *(float4*)(g_el1 + (size_t)nid * 8 + 4) = make_float4(el[4], el[5], el[6], el[7]);
    *(float4*)(g_er1 + (size_t)nid * 8)     = make_float4(er[0], er[1], er[2], er[3]);
    *(float4*)(g_er1 + (size_t)nid * 8 + 4) = make_float4(er[4], er[5], er[6], er[7]);
}

// ---------------- K3: fused layer1 edge pass (16 lanes per edge) ----------------
// agg1[d] += exp(lrelu(el[s]+er[d])) * h1[s] ;  s1[d] += exp(...)
__global__ __launch_bounds__(256) void k_edge1(const int* __restrict__ src,
                                               const int* __restrict__ dst, int e) {
    int gthread = blockIdx.x * 256 + threadIdx.x;
    int eidx = gthread >> 4;                 // 16 lanes per edge
    if (eidx >= e) return;
    int j = gthread & 15;                    // float4 slot 0..15
    int h = j >> 1;                          // head 0..7
    int s = __ldg(src + eidx), d = __ldg(dst + eidx);
    float el = __ldg(g_el1 + (size_t)s * 8 + h);
    float er = __ldg(g_er1 + (size_t)d * 8 + h);
    float ex = __expf(lrelu(el + er));
    float4 hv = __ldg((const float4*)(g_h1 + (size_t)s * D1) + j);
    red4(g_agg1 + (size_t)d * D1 + j * 4,
         make_float4(hv.x * ex, hv.y * ex, hv.z * ex, hv.w * ex));
    if ((j & 1) == 0) redf(g_s1 + (size_t)d * 8 + h, ex);
}

// ---------------- K4: node: ELU(agg1/s1 + b1), GEMM2 (64->40), el2/er2 ----------------
__global__ __launch_bounds__(256) void k_node2(const float* __restrict__ W2,
                                               const float* __restrict__ al2,
                                               const float* __restrict__ ar2,
                                               const float* __restrict__ b1, int n) {
    __shared__ float w2s[64 * 40];
    __shared__ float sal[40], sar[40], sb1[64];
    for (int i = threadIdx.x; i < 64 * 40; i += 256) w2s[i] = W2[i];
    if (threadIdx.x < 40) { sal[threadIdx.x] = al2[threadIdx.x]; sar[threadIdx.x] = ar2[threadIdx.x]; }
    if (threadIdx.x < 64) sb1[threadIdx.x] = b1[threadIdx.x];
    __syncthreads();
    int nid = blockIdx.x * 256 + threadIdx.x;
    if (nid >= n) return;

    float inv[8];
    const float4* sp = (const float4*)(g_s1 + (size_t)nid * 8);
    float4 sv0 = sp[0], sv1 = sp[1];
    inv[0] = sv0.x > 0.f ? 1.f / sv0.x : 0.f;
    inv[1] = sv0.y > 0.f ? 1.f / sv0.y : 0.f;
    inv[2] = sv0.z > 0.f ? 1.f / sv0.z : 0.f;
    inv[3] = sv0.w > 0.f ? 1.f / sv0.w : 0.f;
    inv[4] = sv1.x > 0.f ? 1.f / sv1.x : 0.f;
    inv[5] = sv1.y > 0.f ? 1.f / sv1.y : 0.f;
    inv[6] = sv1.z > 0.f ? 1.f / sv1.z : 0.f;
    inv[7] = sv1.w > 0.f ? 1.f / sv1.w : 0.f;

    float v[64];
    const float4* ap = (const float4*)(g_agg1 + (size_t)nid * D1);
#pragma unroll
    for (int j = 0; j < 16; j++) {
        float4 t = ap[j];
        float iv = inv[j >> 1];
        v[j * 4 + 0] = eluf(t.x * iv + sb1[j * 4 + 0]);
        v[j * 4 + 1] = eluf(t.y * iv + sb1[j * 4 + 1]);
        v[j * 4 + 2] = eluf(t.z * iv + sb1[j * 4 + 2]);
        v[j * 4 + 3] = eluf(t.w * iv + sb1[j * 4 + 3]);
    }
    float ela = 0.f, era = 0.f;
    float* hp = g_h2 + (size_t)nid * D2;
    for (int c = 0; c < D2; c++) {
        float acc = 0.f;
#pragma unroll
        for (int k = 0; k < 64; k++) acc = fmaf(v[k], w2s[k * D2 + c], acc);
        hp[c] = acc;
        ela = fmaf(acc, sal[c], ela);
        era = fmaf(acc, sar[c], era);
    }
    g_el2[nid] = ela;
    g_er2[nid] = era;
}

// ---------------- K5: fused layer2 edge pass (10 lanes per edge, 3 edges/warp) ----------------
__global__ __launch_bounds__(256) void k_edge2(const int* __restrict__ src,
                                               const int* __restrict__ dst, int e) {
    int warp = (blockIdx.x * 256 + threadIdx.x) >> 5;
    int lane = threadIdx.x & 31;
    int g = lane / 10;                       // 0,1,2 (lanes 30,31 idle)
    if (g >= 3) return;
    int eidx = warp * 3 + g;
    if (eidx >= e) return;
    int j = lane - g * 10;                   // float4 slot 0..9
    int s = __ldg(src + eidx), d = __ldg(dst + eidx);
    float ex = __expf(lrelu(__ldg(g_el2 + s) + __ldg(g_er2 + d)));
    float4 hv = __ldg((const float4*)(g_h2 + (size_t)s * D2) + j);
    red4(g_agg2 + (size_t)d * D2 + j * 4,
         make_float4(hv.x * ex, hv.y * ex, hv.z * ex, hv.w * ex));
    if (j == 0) redf(g_s2 + d, ex);
}

// ---------------- K6: final: (agg2/s2 + b2) then log_softmax ----------------
__global__ __launch_bounds__(256) void k_lsm(const float* __restrict__ b2,
                                             float* __restrict__ out, int n) {
    __shared__ float sb2[40];
    if (threadIdx.x < 40) sb2[threadIdx.x] = b2[threadIdx.x];
    __syncthreads();
    int nid = blockIdx.x * 256 + threadIdx.x;
    if (nid >= n) return;
    float sv = g_s2[nid];
    float iv = sv > 0.f ? 1.f / sv : 0.f;
    float v[40];
    const float4* ap = (const float4*)(g_agg2 + (size_t)nid * D2);
    float m = -1e30f;
#pragma unroll
    for (int j = 0; j < 10; j++) {
        float4 t = ap[j];
        v[j*4+0] = t.x * iv + sb2[j*4+0];
        v[j*4+1] = t.y * iv + sb2[j*4+1];
        v[j*4+2] = t.z * iv + sb2[j*4+2];
        v[j*4+3] = t.w * iv + sb2[j*4+3];
        m = fmaxf(m, fmaxf(fmaxf(v[j*4+0], v[j*4+1]), fmaxf(v[j*4+2], v[j*4+3])));
    }
    float s = 0.f;
#pragma unroll
    for (int j = 0; j < 40; j++) s += __expf(v[j] - m);
    float lse = m + logf(s);
    float4* op = (float4*)(out + (size_t)nid * D2);
#pragma unroll
    for (int j = 0; j < 10; j++)
        op[j] = make_float4(v[j*4+0] - lse, v[j*4+1] - lse, v[j*4+2] - lse, v[j*4+3] - lse);
}

// ---------------- launch ----------------
extern "C" void kernel_launch(void* const* d_in, const int* in_sizes, int n_in,
                              void* d_out, int out_size) {
    const float* x   = (const float*)d_in[0];
    const int*   src = (const int*)d_in[1];
    const int*   dst = (const int*)d_in[2];
    const float* W1  = (const float*)d_in[3];
    const float* al1 = (const float*)d_in[4];
    const float* ar1 = (const float*)d_in[5];
    const float* b1  = (const float*)d_in[6];
    const float* W2  = (const float*)d_in[7];
    const float* al2 = (const float*)d_in[8];
    const float* ar2 = (const float*)d_in[9];
    const float* b2  = (const float*)d_in[10];

    int n = in_sizes[0] / INF;
    int e = in_sizes[1];

    int nb_zero  = (n * (D1 / 4) + 255) / 256;
    int nb_node  = (n + 255) / 256;
    int nb_gemm  = (n + 127) / 128;
    int nb_edge1 = (e * 16 + 255) / 256;          // 16 threads per edge
    int nb_edge2 = (e + 23) / 24;                 // 24 edges per 256-thread block

    k_zero <<<nb_zero, 256>>>(n);
    k_gemm1<<<nb_gemm, 256>>>(x, W1, n);
    k_el1  <<<nb_node, 256>>>(al1, ar1, n);
    k_edge1<<<nb_edge1, 256>>>(src, dst, e);
    k_node2<<<nb_node, 256>>>(W2, al2, ar2, b1, n);
    k_edge2<<<nb_edge2, 256>>>(src, dst, e);
    k_lsm  <<<nb_node, 256>>>(b2, (float*)d_out, n);
}

// round 3
// speedup vs baseline: 1.6167x; 1.1622x over previous
#include <cuda_runtime.h>
#include <cuda_bf16.h>

// ---------------- problem constants ----------------
#define NMAX 100000
#define EMAX 1600000
#define INF 512
#define D1 64      // H1*F1 = 8*8
#define H1N 8
#define D2 40      // H2*F2 = 1*40

// ---------------- device scratch ----------------
__device__ __align__(16) float g_h1  [NMAX * D1];
__device__ __align__(16) float g_el1 [NMAX * H1N];
__device__ __align__(16) float g_er1 [NMAX * H1N];
__device__ __align__(16) float g_agg1[NMAX * D1];   // normalized layer1 output (pre-bias)
__device__ __align__(16) float g_h2  [NMAX * D2];
__device__ __align__(16) float g_el2 [NMAX];
__device__ __align__(16) float g_er2 [NMAX];
__device__ __align__(16) float g_agg2[NMAX * D2];   // normalized layer2 output (pre-bias)
// CSR scratch
__device__ int g_hist[NMAX];
__device__ int g_rowstart[NMAX];
__device__ int g_cursor[NMAX];       // after scatter: row end
__device__ int g_sorted[EMAX];       // src ids grouped by dst
__device__ int g_counter;

// ---------------- helpers ----------------
__device__ __forceinline__ unsigned long long pk(float a, float b) {
    unsigned long long r;
    asm("mov.b64 %0, {%1, %2};" : "=l"(r) : "f"(a), "f"(b));
    return r;
}
__device__ __forceinline__ float2 upk(unsigned long long v) {
    float2 r;
    asm("mov.b64 {%0, %1}, %2;" : "=f"(r.x), "=f"(r.y) : "l"(v));
    return r;
}
__device__ __forceinline__ void fma2(unsigned long long& d, unsigned long long a, unsigned long long b) {
    asm("fma.rn.f32x2 %0, %1, %2, %3;" : "=l"(d) : "l"(a), "l"(b), "l"(d));
}
__device__ __forceinline__ float lrelu(float v) { return v >= 0.f ? v : 0.2f * v; }
__device__ __forceinline__ float eluf(float v)  { return v > 0.f ? v : expm1f(v); }

// ---------------- K0: zero hist + counter ----------------
__global__ void k_zero(int n) {
    int i = blockIdx.x * 256 + threadIdx.x;
    if (i < n) g_hist[i] = 0;
    if (i == 0) g_counter = 0;
}

// ---------------- K_hist: in-degree histogram ----------------
__global__ __launch_bounds__(256) void k_hist(const int* __restrict__ dst, int e) {
    int i = blockIdx.x * 256 + threadIdx.x;
    if (i < e) atomicAdd(&g_hist[dst[i]], 1);
}

// ---------------- K_rowalloc: warp-scanned row offsets ----------------
__global__ __launch_bounds__(256) void k_rowalloc(int n) {
    int d = blockIdx.x * 256 + threadIdx.x;
    int lane = threadIdx.x & 31;
    int c = (d < n) ? g_hist[d] : 0;
    int sum = c;
#pragma unroll
    for (int off = 1; off < 32; off <<= 1) {
        int v = __shfl_up_sync(0xffffffffu, sum, off);
        if (lane >= off) sum += v;
    }
    int total = __shfl_sync(0xffffffffu, sum, 31);
    int base = 0;
    if (lane == 31) base = atomicAdd(&g_counter, total);
    base = __shfl_sync(0xffffffffu, base, 31);
    if (d < n) {
        int st = base + sum - c;
        g_rowstart[d] = st;
        g_cursor[d]   = st;
    }
}

// ---------------- K_scatter: group src by dst ----------------
__global__ __launch_bounds__(256) void k_scatter(const int* __restrict__ src,
                                                 const int* __restrict__ dst, int e) {
    int i = blockIdx.x * 256 + threadIdx.x;
    if (i >= e) return;
    int p = atomicAdd(&g_cursor[dst[i]], 1);
    g_sorted[p] = src[i];
}

// ---------------- K1: h1 = x @ W1   (100k x 512) @ (512 x 64), f32x2 FMA ----------------
__global__ __launch_bounds__(256) void k_gemm1(const float* __restrict__ x,
                                               const float* __restrict__ W1, int n) {
    __shared__ __align__(16) float xs[128][40];
    __shared__ __align__(16) float ws[32][64];
    const int tx = threadIdx.x;
    const int row0 = blockIdx.x * 128;
    const int rg = (tx >> 3) * 4;
    const int cg = (tx & 7) * 8;

    unsigned long long acc[4][4];
#pragma unroll
    for (int i = 0; i < 4; i++)
#pragma unroll
        for (int j = 0; j < 4; j++) acc[i][j] = 0ull;

    for (int k0 = 0; k0 < INF; k0 += 32) {
#pragma unroll
        for (int it = 0; it < 4; it++) {
            int slot = tx + it * 256;
            int r = slot >> 3;
            int kk = (slot & 7) << 2;
            float4 v = make_float4(0.f, 0.f, 0.f, 0.f);
            int grow = row0 + r;
            if (grow < n) v = *(const float4*)(x + (size_t)grow * INF + k0 + kk);
            *(float4*)&xs[r][kk] = v;
        }
#pragma unroll
        for (int it = 0; it < 2; it++) {
            int slot = tx + it * 256;
            int kk = slot >> 4;
            int cc = (slot & 15) << 2;
            *(float4*)&ws[kk][cc] = *(const float4*)(W1 + (size_t)(k0 + kk) * D1 + cc);
        }
        __syncthreads();

#pragma unroll
        for (int k4 = 0; k4 < 32; k4 += 4) {
            float4 A[4];
#pragma unroll
            for (int i = 0; i < 4; i++) A[i] = *(const float4*)&xs[rg + i][k4];
#pragma unroll
            for (int kk = 0; kk < 4; kk++) {
                ulonglong2 B0 = *(const ulonglong2*)&ws[k4 + kk][cg];
                ulonglong2 B1 = *(const ulonglong2*)&ws[k4 + kk][cg + 4];
#pragma unroll
                for (int i = 0; i < 4; i++) {
                    float ai = ((const float*)&A[i])[kk];
                    unsigned long long pa = pk(ai, ai);
                    fma2(acc[i][0], pa, B0.x);
                    fma2(acc[i][1], pa, B0.y);
                    fma2(acc[i][2], pa, B1.x);
                    fma2(acc[i][3], pa, B1.y);
                }
            }
        }
        __syncthreads();
    }

#pragma unroll
    for (int i = 0; i < 4; i++) {
        int grow = row0 + rg + i;
        if (grow < n) {
            float2 v0 = upk(acc[i][0]), v1 = upk(acc[i][1]);
            float2 v2 = upk(acc[i][2]), v3 = upk(acc[i][3]);
            *(float4*)(g_h1 + (size_t)grow * D1 + cg)     = make_float4(v0.x, v0.y, v1.x, v1.y);
            *(float4*)(g_h1 + (size_t)grow * D1 + cg + 4) = make_float4(v2.x, v2.y, v3.x, v3.y);
        }
    }
}

// ---------------- K2: per-node attention dots el1/er1 ----------------
__global__ __launch_bounds__(256) void k_el1(const float* __restrict__ al1,
                                             const float* __restrict__ ar1, int n) {
    __shared__ float sa[64], sr[64];
    if (threadIdx.x < 64) { sa[threadIdx.x] = al1[threadIdx.x]; sr[threadIdx.x] = ar1[threadIdx.x]; }
    __syncthreads();
    int nid = blockIdx.x * 256 + threadIdx.x;
    if (nid >= n) return;
    const float4* hp = (const float4*)(g_h1 + (size_t)nid * D1);
    float el[8], er[8];
#pragma unroll
    for (int h = 0; h < 8; h++) {
        float4 t0 = hp[h * 2], t1 = hp[h * 2 + 1];
        int b = h * 8;
        el[h] = t0.x*sa[b] + t0.y*sa[b+1] + t0.z*sa[b+2] + t0.w*sa[b+3]
              + t1.x*sa[b+4] + t1.y*sa[b+5] + t1.z*sa[b+6] + t1.w*sa[b+7];
        er[h] = t0.x*sr[b] + t0.y*sr[b+1] + t0.z*sr[b+2] + t0.w*sr[b+3]
              + t1.x*sr[b+4] + t1.y*sr[b+5] + t1.z*sr[b+6] + t1.w*sr[b+7];
    }
    *(float4*)(g_el1 + (size_t)nid * 8)     = make_float4(el[0], el[1], el[2], el[3]);
    *(float4*)(g_el1 + (size_t)nid * 8 + 4) = make_float4(el[4], el[5], el[6], el[7]);
    *(float4*)(g_er1 + (size_t)nid * 8)     = make_float4(er[0], er[1], er[2], er[3]);
    *(float4*)(g_er1 + (size_t)nid * 8 + 4) = make_float4(er[4], er[5], er[6], er[7]);
}

// ---------------- K3: layer1 CSR aggregation (half-warp per dst) ----------------
// agg1[d] = (sum_e ex * h1[s]) / (sum_e ex), normalized in registers.
__global__ __launch_bounds__(256) void k_agg1(int n) {
    int t = blockIdx.x * 256 + threadIdx.x;
    int d = t >> 4;
    if (d >= n) return;
    int j = t & 15;          // float4 slot
    int h = j >> 1;          // head
    float er = g_er1[(size_t)d * 8 + h];
    int k0 = g_rowstart[d], k1 = g_cursor[d];
    float4 acc = make_float4(0.f, 0.f, 0.f, 0.f);
    float denom = 0.f;
    for (int k = k0; k < k1; k++) {
        int s = __ldg(g_sorted + k);
        float ex = __expf(lrelu(__ldg(g_el1 + (size_t)s * 8 + h) + er));
        float4 hv = __ldg((const float4*)(g_h1 + (size_t)s * D1) + j);
        acc.x = fmaf(ex, hv.x, acc.x);
        acc.y = fmaf(ex, hv.y, acc.y);
        acc.z = fmaf(ex, hv.z, acc.z);
        acc.w = fmaf(ex, hv.w, acc.w);
        denom += ex;
    }
    float iv = denom > 0.f ? __fdividef(1.f, denom) : 0.f;
    *(float4*)(g_agg1 + (size_t)d * D1 + j * 4) =
        make_float4(acc.x * iv, acc.y * iv, acc.z * iv, acc.w * iv);
}

// ---------------- K4: node: ELU(agg1 + b1), GEMM2 (64->40), el2/er2 ----------------
__global__ __launch_bounds__(256) void k_node2(const float* __restrict__ W2,
                                               const float* __restrict__ al2,
                                               const float* __restrict__ ar2,
                                               const float* __restrict__ b1, int n) {
    __shared__ float w2s[64 * 40];
    __shared__ float sal[40], sar[40], sb1[64];
    for (int i = threadIdx.x; i < 64 * 40; i += 256) w2s[i] = W2[i];
    if (threadIdx.x < 40) { sal[threadIdx.x] = al2[threadIdx.x]; sar[threadIdx.x] = ar2[threadIdx.x]; }
    if (threadIdx.x < 64) sb1[threadIdx.x] = b1[threadIdx.x];
    __syncthreads();
    int nid = blockIdx.x * 256 + threadIdx.x;
    if (nid >= n) return;

    float v[64];
    const float4* ap = (const float4*)(g_agg1 + (size_t)nid * D1);
#pragma unroll
    for (int j = 0; j < 16; j++) {
        float4 t = ap[j];
        v[j * 4 + 0] = eluf(t.x + sb1[j * 4 + 0]);
        v[j * 4 + 1] = eluf(t.y + sb1[j * 4 + 1]);
        v[j * 4 + 2] = eluf(t.z + sb1[j * 4 + 2]);
        v[j * 4 + 3] = eluf(t.w + sb1[j * 4 + 3]);
    }
    float ela = 0.f, era = 0.f;
    float* hp = g_h2 + (size_t)nid * D2;
    for (int c = 0; c < D2; c++) {
        float acc = 0.f;
#pragma unroll
        for (int k = 0; k < 64; k++) acc = fmaf(v[k], w2s[k * D2 + c], acc);
        hp[c] = acc;
        ela = fmaf(acc, sal[c], ela);
        era = fmaf(acc, sar[c], era);
    }
    g_el2[nid] = ela;
    g_er2[nid] = era;
}

// ---------------- K5: layer2 CSR aggregation (warp per dst, 20 lanes) ----------------
__global__ __launch_bounds__(256) void k_agg2(int n) {
    int d = (blockIdx.x * 256 + threadIdx.x) >> 5;
    int lane = threadIdx.x & 31;
    if (d >= n || lane >= 20) return;
    float er = g_er2[d];
    int k0 = g_rowstart[d], k1 = g_cursor[d];
    float2 acc = make_float2(0.f, 0.f);
    float denom = 0.f;
    for (int k = k0; k < k1; k++) {
        int s = __ldg(g_sorted + k);
        float ex = __expf(lrelu(__ldg(g_el2 + s) + er));
        float2 hv = __ldg((const float2*)(g_h2 + (size_t)s * D2) + lane);
        acc.x = fmaf(ex, hv.x, acc.x);
        acc.y = fmaf(ex, hv.y, acc.y);
        denom += ex;
    }
    float iv = denom > 0.f ? __fdividef(1.f, denom) : 0.f;
    *(float2*)(g_agg2 + (size_t)d * D2 + lane * 2) = make_float2(acc.x * iv, acc.y * iv);
}

// ---------------- K6: final: (agg2 + b2) then log_softmax ----------------
__global__ __launch_bounds__(256) void k_lsm(const float* __restrict__ b2,
                                             float* __restrict__ out, int n) {
    __shared__ float sb2[40];
    if (threadIdx.x < 40) sb2[threadIdx.x] = b2[threadIdx.x];
    __syncthreads();
    int nid = blockIdx.x * 256 + threadIdx.x;
    if (nid >= n) return;
    float v[40];
    const float4* ap = (const float4*)(g_agg2 + (size_t)nid * D2);
    float m = -1e30f;
#pragma unroll
    for (int j = 0; j < 10; j++) {
        float4 t = ap[j];
        v[j*4+0] = t.x + sb2[j*4+0];
        v[j*4+1] = t.y + sb2[j*4+1];
        v[j*4+2] = t.z + sb2[j*4+2];
        v[j*4+3] = t.w + sb2[j*4+3];
        m = fmaxf(m, fmaxf(fmaxf(v[j*4+0], v[j*4+1]), fmaxf(v[j*4+2], v[j*4+3])));
    }
    float s = 0.f;
#pragma unroll
    for (int j = 0; j < 40; j++) s += __expf(v[j] - m);
    float lse = m + logf(s);
    float4* op = (float4*)(out + (size_t)nid * D2);
#pragma unroll
    for (int j = 0; j < 10; j++)
        op[j] = make_float4(v[j*4+0] - lse, v[j*4+1] - lse, v[j*4+2] - lse, v[j*4+3] - lse);
}

// ---------------- launch ----------------
extern "C" void kernel_launch(void* const* d_in, const int* in_sizes, int n_in,
                              void* d_out, int out_size) {
    const float* x   = (const float*)d_in[0];
    const int*   src = (const int*)d_in[1];
    const int*   dst = (const int*)d_in[2];
    const float* W1  = (const float*)d_in[3];
    const float* al1 = (const float*)d_in[4];
    const float* ar1 = (const float*)d_in[5];
    const float* b1  = (const float*)d_in[6];
    const float* W2  = (const float*)d_in[7];
    const float* al2 = (const float*)d_in[8];
    const float* ar2 = (const float*)d_in[9];
    const float* b2  = (const float*)d_in[10];

    int n = in_sizes[0] / INF;
    int e = in_sizes[1];

    int nb_node  = (n + 255) / 256;
    int nb_edge  = (e + 255) / 256;
    int nb_gemm  = (n + 127) / 128;
    int nb_agg1  = (n * 16 + 255) / 256;
    int nb_agg2  = (n * 32 + 255) / 256;

    k_zero    <<<nb_node, 256>>>(n);
    k_hist    <<<nb_edge, 256>>>(dst, e);
    k_rowalloc<<<nb_node, 256>>>(n);
    k_scatter <<<nb_edge, 256>>>(src, dst, e);
    k_gemm1   <<<nb_gemm, 256>>>(x, W1, n);
    k_el1     <<<nb_node, 256>>>(al1, ar1, n);
    k_agg1    <<<nb_agg1, 256>>>(n);
    k_node2   <<<nb_node, 256>>>(W2, al2, ar2, b1, n);
    k_agg2    <<<nb_agg2, 256>>>(n);
    k_lsm     <<<nb_node, 256>>>(b2, (float*)d_out, n);
}

// round 4
// speedup vs baseline: 1.6239x; 1.0045x over previous
#include <cuda_runtime.h>
#include <cuda_bf16.h>

// ---------------- problem constants ----------------
#define NMAX 100000
#define EMAX 1600000
#define INF 512
#define D1 64      // H1*F1 = 8*8
#define H1N 8
#define D2 40      // H2*F2 = 1*40

// ---------------- device scratch ----------------
__device__ __align__(16) float g_h1  [NMAX * D1];
__device__ __align__(16) float g_el1 [NMAX * H1N];
__device__ __align__(16) float g_er1 [NMAX * H1N];
__device__ __align__(16) float g_agg1[NMAX * D1];   // normalized layer1 output (pre-bias)
__device__ __align__(16) float g_h2  [NMAX * D2];
__device__ __align__(16) float g_el2 [NMAX];
__device__ __align__(16) float g_er2 [NMAX];
__device__ __align__(16) float g_agg2[NMAX * D2];   // normalized layer2 output (pre-bias)
// CSR scratch
__device__ int g_hist[NMAX];
__device__ int g_rowstart[NMAX];
__device__ int g_cursor[NMAX];       // after scatter: row end
__device__ int g_sorted[EMAX];       // src ids grouped by dst
__device__ int g_counter;

// ---------------- helpers ----------------
__device__ __forceinline__ unsigned long long pk(float a, float b) {
    unsigned long long r;
    asm("mov.b64 %0, {%1, %2};" : "=l"(r) : "f"(a), "f"(b));
    return r;
}
__device__ __forceinline__ float2 upk(unsigned long long v) {
    float2 r;
    asm("mov.b64 {%0, %1}, %2;" : "=f"(r.x), "=f"(r.y) : "l"(v));
    return r;
}
__device__ __forceinline__ void fma2(unsigned long long& d, unsigned long long a, unsigned long long b) {
    asm("fma.rn.f32x2 %0, %1, %2, %3;" : "=l"(d) : "l"(a), "l"(b), "l"(d));
}
__device__ __forceinline__ float lrelu(float v) { return v >= 0.f ? v : 0.2f * v; }
__device__ __forceinline__ float eluf(float v)  { return v > 0.f ? v : expm1f(v); }

// ---------------- K0: zero hist + counter ----------------
__global__ void k_zero(int n) {
    int i = blockIdx.x * 256 + threadIdx.x;
    if (i < n) g_hist[i] = 0;
    if (i == 0) g_counter = 0;
}

// ---------------- K_hist: in-degree histogram ----------------
__global__ __launch_bounds__(256) void k_hist(const int* __restrict__ dst, int e) {
    int i = blockIdx.x * 256 + threadIdx.x;
    if (i < e) atomicAdd(&g_hist[dst[i]], 1);
}

// ---------------- K_rowalloc: warp-scanned row offsets ----------------
__global__ __launch_bounds__(256) void k_rowalloc(int n) {
    int d = blockIdx.x * 256 + threadIdx.x;
    int lane = threadIdx.x & 31;
    int c = (d < n) ? g_hist[d] : 0;
    int sum = c;
#pragma unroll
    for (int off = 1; off < 32; off <<= 1) {
        int v = __shfl_up_sync(0xffffffffu, sum, off);
        if (lane >= off) sum += v;
    }
    int total = __shfl_sync(0xffffffffu, sum, 31);
    int base = 0;
    if (lane == 31) base = atomicAdd(&g_counter, total);
    base = __shfl_sync(0xffffffffu, base, 31);
    if (d < n) {
        int st = base + sum - c;
        g_rowstart[d] = st;
        g_cursor[d]   = st;
    }
}

// ---------------- K_scatter: group src by dst ----------------
__global__ __launch_bounds__(256) void k_scatter(const int* __restrict__ src,
                                                 const int* __restrict__ dst, int e) {
    int i = blockIdx.x * 256 + threadIdx.x;
    if (i >= e) return;
    int p = atomicAdd(&g_cursor[dst[i]], 1);
    g_sorted[p] = src[i];
}

// ---------------- K1: h1 = x @ W1   (100k x 512) @ (512 x 64), f32x2 FMA ----------------
__global__ __launch_bounds__(256) void k_gemm1(const float* __restrict__ x,
                                               const float* __restrict__ W1, int n) {
    __shared__ __align__(16) float xs[128][40];
    __shared__ __align__(16) float ws[32][64];
    const int tx = threadIdx.x;
    const int row0 = blockIdx.x * 128;
    const int rg = (tx >> 3) * 4;
    const int cg = (tx & 7) * 8;

    unsigned long long acc[4][4];
#pragma unroll
    for (int i = 0; i < 4; i++)
#pragma unroll
        for (int j = 0; j < 4; j++) acc[i][j] = 0ull;

    for (int k0 = 0; k0 < INF; k0 += 32) {
#pragma unroll
        for (int it = 0; it < 4; it++) {
            int slot = tx + it * 256;
            int r = slot >> 3;
            int kk = (slot & 7) << 2;
            float4 v = make_float4(0.f, 0.f, 0.f, 0.f);
            int grow = row0 + r;
            if (grow < n) v = *(const float4*)(x + (size_t)grow * INF + k0 + kk);
            *(float4*)&xs[r][kk] = v;
        }
#pragma unroll
        for (int it = 0; it < 2; it++) {
            int slot = tx + it * 256;
            int kk = slot >> 4;
            int cc = (slot & 15) << 2;
            *(float4*)&ws[kk][cc] = *(const float4*)(W1 + (size_t)(k0 + kk) * D1 + cc);
        }
        __syncthreads();

#pragma unroll
        for (int k4 = 0; k4 < 32; k4 += 4) {
            float4 A[4];
#pragma unroll
            for (int i = 0; i < 4; i++) A[i] = *(const float4*)&xs[rg + i][k4];
#pragma unroll
            for (int kk = 0; kk < 4; kk++) {
                ulonglong2 B0 = *(const ulonglong2*)&ws[k4 + kk][cg];
                ulonglong2 B1 = *(const ulonglong2*)&ws[k4 + kk][cg + 4];
#pragma unroll
                for (int i = 0; i < 4; i++) {
                    float ai = ((const float*)&A[i])[kk];
                    unsigned long long pa = pk(ai, ai);
                    fma2(acc[i][0], pa, B0.x);
                    fma2(acc[i][1], pa, B0.y);
                    fma2(acc[i][2], pa, B1.x);
                    fma2(acc[i][3], pa, B1.y);
                }
            }
        }
        __syncthreads();
    }

#pragma unroll
    for (int i = 0; i < 4; i++) {
        int grow = row0 + rg + i;
        if (grow < n) {
            float2 v0 = upk(acc[i][0]), v1 = upk(acc[i][1]);
            float2 v2 = upk(acc[i][2]), v3 = upk(acc[i][3]);
            *(float4*)(g_h1 + (size_t)grow * D1 + cg)     = make_float4(v0.x, v0.y, v1.x, v1.y);
            *(float4*)(g_h1 + (size_t)grow * D1 + cg + 4) = make_float4(v2.x, v2.y, v3.x, v3.y);
        }
    }
}

// ---------------- K2: per-node attention dots el1/er1 ----------------
__global__ __launch_bounds__(256) void k_el1(const float* __restrict__ al1,
                                             const float* __restrict__ ar1, int n) {
    __shared__ float sa[64], sr[64];
    if (threadIdx.x < 64) { sa[threadIdx.x] = al1[threadIdx.x]; sr[threadIdx.x] = ar1[threadIdx.x]; }
    __syncthreads();
    int nid = blockIdx.x * 256 + threadIdx.x;
    if (nid >= n) return;
    const float4* hp = (const float4*)(g_h1 + (size_t)nid * D1);
    float el[8], er[8];
#pragma unroll
    for (int h = 0; h < 8; h++) {
        float4 t0 = hp[h * 2], t1 = hp[h * 2 + 1];
        int b = h * 8;
        el[h] = t0.x*sa[b] + t0.y*sa[b+1] + t0.z*sa[b+2] + t0.w*sa[b+3]
              + t1.x*sa[b+4] + t1.y*sa[b+5] + t1.z*sa[b+6] + t1.w*sa[b+7];
        er[h] = t0.x*sr[b] + t0.y*sr[b+1] + t0.z*sr[b+2] + t0.w*sr[b+3]
              + t1.x*sr[b+4] + t1.y*sr[b+5] + t1.z*sr[b+6] + t1.w*sr[b+7];
    }
    *(float4*)(g_el1 + (size_t)nid * 8)     = make_float4(el[0], el[1], el[2], el[3]);
    *(float4*)(g_el1 + (size_t)nid * 8 + 4) = make_float4(el[4], el[5], el[6], el[7]);
    *(float4*)(g_er1 + (size_t)nid * 8)     = make_float4(er[0], er[1], er[2], er[3]);
    *(float4*)(g_er1 + (size_t)nid * 8 + 4) = make_float4(er[4], er[5], er[6], er[7]);
}

// ---------------- K3: layer1 CSR aggregation (half-warp per dst) ----------------
// agg1[d] = (sum_e ex * h1[s]) / (sum_e ex), normalized in registers.
__global__ __launch_bounds__(256) void k_agg1(int n) {
    int t = blockIdx.x * 256 + threadIdx.x;
    int d = t >> 4;
    if (d >= n) return;
    int j = t & 15;          // float4 slot
    int h = j >> 1;          // head
    float er = g_er1[(size_t)d * 8 + h];
    int k0 = g_rowstart[d], k1 = g_cursor[d];
    float4 acc = make_float4(0.f, 0.f, 0.f, 0.f);
    float denom = 0.f;
    for (int k = k0; k < k1; k++) {
        int s = __ldg(g_sorted + k);
        float ex = __expf(lrelu(__ldg(g_el1 + (size_t)s * 8 + h) + er));
        float4 hv = __ldg((const float4*)(g_h1 + (size_t)s * D1) + j);
        acc.x = fmaf(ex, hv.x, acc.x);
        acc.y = fmaf(ex, hv.y, acc.y);
        acc.z = fmaf(ex, hv.z, acc.z);
        acc.w = fmaf(ex, hv.w, acc.w);
        denom += ex;
    }
    float iv = denom > 0.f ? __fdividef(1.f, denom) : 0.f;
    *(float4*)(g_agg1 + (size_t)d * D1 + j * 4) =
        make_float4(acc.x * iv, acc.y * iv, acc.z * iv, acc.w * iv);
}

// ---------------- K4: node: ELU(agg1 + b1), GEMM2 (64->40), el2/er2 ----------------
__global__ __launch_bounds__(256) void k_node2(const float* __restrict__ W2,
                                               const float* __restrict__ al2,
                                               const float* __restrict__ ar2,
                                               const float* __restrict__ b1, int n) {
    __shared__ float w2s[64 * 40];
    __shared__ float sal[40], sar[40], sb1[64];
    for (int i = threadIdx.x; i < 64 * 40; i += 256) w2s[i] = W2[i];
    if (threadIdx.x < 40) { sal[threadIdx.x] = al2[threadIdx.x]; sar[threadIdx.x] = ar2[threadIdx.x]; }
    if (threadIdx.x < 64) sb1[threadIdx.x] = b1[threadIdx.x];
    __syncthreads();
    int nid = blockIdx.x * 256 + threadIdx.x;
    if (nid >= n) return;

    float v[64];
    const float4* ap = (const float4*)(g_agg1 + (size_t)nid * D1);
#pragma unroll
    for (int j = 0; j < 16; j++) {
        float4 t = ap[j];
        v[j * 4 + 0] = eluf(t.x + sb1[j * 4 + 0]);
        v[j * 4 + 1] = eluf(t.y + sb1[j * 4 + 1]);
        v[j * 4 + 2] = eluf(t.z + sb1[j * 4 + 2]);
        v[j * 4 + 3] = eluf(t.w + sb1[j * 4 + 3]);
    }
    float ela = 0.f, era = 0.f;
    float* hp = g_h2 + (size_t)nid * D2;
    for (int c = 0; c < D2; c++) {
        float acc = 0.f;
#pragma unroll
        for (int k = 0; k < 64; k++) acc = fmaf(v[k], w2s[k * D2 + c], acc);
        hp[c] = acc;
        ela = fmaf(acc, sal[c], ela);
        era = fmaf(acc, sar[c], era);
    }
    g_el2[nid] = ela;
    g_er2[nid] = era;
}

// ---------------- K5: layer2 CSR aggregation (warp per dst, 20 lanes) ----------------
__global__ __launch_bounds__(256) void k_agg2(int n) {
    int d = (blockIdx.x * 256 + threadIdx.x) >> 5;
    int lane = threadIdx.x & 31;
    if (d >= n || lane >= 20) return;
    float er = g_er2[d];
    int k0 = g_rowstart[d], k1 = g_cursor[d];
    float2 acc = make_float2(0.f, 0.f);
    float denom = 0.f;
    for (int k = k0; k < k1; k++) {
        int s = __ldg(g_sorted + k);
        float ex = __expf(lrelu(__ldg(g_el2 + s) + er));
        float2 hv = __ldg((const float2*)(g_h2 + (size_t)s * D2) + lane);
        acc.x = fmaf(ex, hv.x, acc.x);
        acc.y = fmaf(ex, hv.y, acc.y);
        denom += ex;
    }
    float iv = denom > 0.f ? __fdividef(1.f, denom) : 0.f;
    *(float2*)(g_agg2 + (size_t)d * D2 + lane * 2) = make_float2(acc.x * iv, acc.y * iv);
}

// ---------------- K6: final: (agg2 + b2) then log_softmax ----------------
__global__ __launch_bounds__(256) void k_lsm(const float* __restrict__ b2,
                                             float* __restrict__ out, int n) {
    __shared__ float sb2[40];
    if (threadIdx.x < 40) sb2[threadIdx.x] = b2[threadIdx.x];
    __syncthreads();
    int nid = blockIdx.x * 256 + threadIdx.x;
    if (nid >= n) return;
    float v[40];
    const float4* ap = (const float4*)(g_agg2 + (size_t)nid * D2);
    float m = -1e30f;
#pragma unroll
    for (int j = 0; j < 10; j++) {
        float4 t = ap[j];
        v[j*4+0] = t.x + sb2[j*4+0];
        v[j*4+1] = t.y + sb2[j*4+1];
        v[j*4+2] = t.z + sb2[j*4+2];
        v[j*4+3] = t.w + sb2[j*4+3];
        m = fmaxf(m, fmaxf(fmaxf(v[j*4+0], v[j*4+1]), fmaxf(v[j*4+2], v[j*4+3])));
    }
    float s = 0.f;
#pragma unroll
    for (int j = 0; j < 40; j++) s += __expf(v[j] - m);
    float lse = m + logf(s);
    float4* op = (float4*)(out + (size_t)nid * D2);
#pragma unroll
    for (int j = 0; j < 10; j++)
        op[j] = make_float4(v[j*4+0] - lse, v[j*4+1] - lse, v[j*4+2] - lse, v[j*4+3] - lse);
}

// ---------------- launch ----------------
extern "C" void kernel_launch(void* const* d_in, const int* in_sizes, int n_in,
                              void* d_out, int out_size) {
    const float* x   = (const float*)d_in[0];
    const int*   src = (const int*)d_in[1];
    const int*   dst = (const int*)d_in[2];
    const float* W1  = (const float*)d_in[3];
    const float* al1 = (const float*)d_in[4];
    const float* ar1 = (const float*)d_in[5];
    const float* b1  = (const float*)d_in[6];
    const float* W2  = (const float*)d_in[7];
    const float* al2 = (const float*)d_in[8];
    const float* ar2 = (const float*)d_in[9];
    const float* b2  = (const float*)d_in[10];

    int n = in_sizes[0] / INF;
    int e = in_sizes[1];

    int nb_node  = (n + 255) / 256;
    int nb_edge  = (e + 255) / 256;
    int nb_gemm  = (n + 127) / 128;
    int nb_agg1  = (n * 16 + 255) / 256;
    int nb_agg2  = (n * 32 + 255) / 256;

    k_zero    <<<nb_node, 256>>>(n);
    k_hist    <<<nb_edge, 256>>>(dst, e);
    k_rowalloc<<<nb_node, 256>>>(n);
    k_scatter <<<nb_edge, 256>>>(src, dst, e);
    k_gemm1   <<<nb_gemm, 256>>>(x, W1, n);
    k_el1     <<<nb_node, 256>>>(al1, ar1, n);
    k_agg1    <<<nb_agg1, 256>>>(n);
    k_node2   <<<nb_node, 256>>>(W2, al2, ar2, b1, n);
    k_agg2    <<<nb_agg2, 256>>>(n);
    k_lsm     <<<nb_node, 256>>>(b2, (float*)d_out, n);
}